// round 16
// baseline (speedup 1.0000x reference)
#include <cuda_runtime.h>
#include <cuda_fp16.h>
#include <cstdint>
#include <cstddef>

// ---------------------------------------------------------------------------
// Problem constants
// ---------------------------------------------------------------------------
#define BB   32
#define NN   144
#define EE   127
#define DD   512
#define HH   8
#define DK   64
#define DV   64
#define FF   16384
#define LL   4
#define MROWS (BB*NN)        // 4608
#define KENC  (EE+1)         // 128

// ---------------------------------------------------------------------------
// Scratch (static device globals)
// ---------------------------------------------------------------------------
__device__ float g_xe  [MROWS * DD];
__device__ float g_qkv [MROWS * 3 * DD];
__device__ float g_kv4 [(size_t)MROWS * 4 * 1024];   // all-layer KV: [row, l*1024 + {k|v}]
__device__ float g_a2  [MROWS * DD];
__device__ float g_ao  [MROWS * DD];
__device__ float g_part[2 * MROWS * DD];
__device__ float g_dec [MROWS * 128];

// fp16 activations
__device__ __half g_xp_h [MROWS * KENC], g_xp_l [MROWS * KENC];
__device__ __half g_xe_h [MROWS * DD];
__device__ __half g_cur_h[MROWS * DD], g_cur_l[MROWS * DD];
__device__ __half g_qln_h[MROWS * DD];
__device__ __half g_at_h [MROWS * DD];
__device__ __half g_a2_h [MROWS * DD];
__device__ __half g_ao_h [MROWS * DD];
__device__ __half g_hid_h[(size_t)MROWS * FF];

// Transposed fp16 weights, [Nrows, K] row-major per layer.
__device__ __half g_wqkvT[(size_t)LL * 3 * DD * DD];
__device__ __half g_woT  [(size_t)LL * DD * DD];
__device__ __half g_w1T  [(size_t)LL * FF * DD];
__device__ __half g_w2T  [(size_t)LL * DD * FF];
__device__ __half g_wencT[DD * KENC];
__device__ __half g_wdecT[128 * DD];

// ---------------------------------------------------------------------------
// Small helpers
// ---------------------------------------------------------------------------
__device__ __forceinline__ uint32_t smem_u32(const void* p) {
    uint32_t a;
    asm("{ .reg .u64 t; cvta.to.shared.u64 t, %1; cvt.u32.u64 %0, t; }" : "=r"(a) : "l"(p));
    return a;
}
__device__ __forceinline__ void cpa16(uint32_t d, const void* s) {
    asm volatile("cp.async.cg.shared.global [%0], [%1], 16;" :: "r"(d), "l"(s));
}
__device__ __forceinline__ void cpa_commit() {
    asm volatile("cp.async.commit_group;" ::: "memory");
}
__device__ __forceinline__ void ldsm4(uint32_t a, uint32_t& r0, uint32_t& r1,
                                      uint32_t& r2, uint32_t& r3) {
    asm volatile("ldmatrix.sync.aligned.m8n8.x4.shared.b16 {%0,%1,%2,%3}, [%4];"
                 : "=r"(r0), "=r"(r1), "=r"(r2), "=r"(r3) : "r"(a));
}
__device__ __forceinline__ void mma16816(float* c, const uint32_t* a,
                                         uint32_t b0, uint32_t b1) {
    asm volatile("mma.sync.aligned.m16n8k16.row.col.f32.f16.f16.f32 "
                 "{%0,%1,%2,%3},{%4,%5,%6,%7},{%8,%9},{%0,%1,%2,%3};"
                 : "+f"(c[0]), "+f"(c[1]), "+f"(c[2]), "+f"(c[3])
                 : "r"(a[0]), "r"(a[1]), "r"(a[2]), "r"(a[3]), "r"(b0), "r"(b1));
}
__device__ __forceinline__ void split2(float x, float y, __half2& h, __half2& l) {
    __half hx = __float2half_rn(x);
    __half hy = __float2half_rn(y);
    h = __halves2half2(hx, hy);
    l = __halves2half2(__float2half_rn(x - __half2float(hx)),
                       __float2half_rn(y - __half2float(hy)));
}

#define SA    40
#define TILEB (128 * SA * 2)        // 10240 bytes

// ---------------------------------------------------------------------------
// Small-N 1-pass fp16 GEMM: 128x128 CTA tile, 256 threads, 8 warps (2M x 4N),
// warp tile 64x32, BK=64, NST=2, 2 CTAs/SM. Split-K via gridDim.z.
// ---------------------------------------------------------------------------
#define STG1S  (4 * TILEB)          // A0,A1,B0,B1 = 40960
#define SMEM1S (2 * STG1S)          // 81920

__global__ void __launch_bounds__(256, 2)
hgemm1s_kernel(const __half* __restrict__ Ah, const __half* __restrict__ Bh,
               const float* __restrict__ bias,
               float* __restrict__ C, __half* __restrict__ Ch,
               int M, int N, int K, int relu)
{
    const uint32_t OF_A0 = 0, OF_A1 = TILEB, OF_B0 = 2 * TILEB, OF_B1 = 3 * TILEB;

    extern __shared__ __half smraw[];
    const uint32_t sb = smem_u32(smraw);

    const int tid  = threadIdx.x;
    const int lane = tid & 31;
    const int wid  = tid >> 5;
    const int wm   = wid >> 2;
    const int wn   = wid & 3;
    const int bm   = blockIdx.y * 128;
    const int bn   = blockIdx.x * 128;

    const int kc   = K / gridDim.z;
    const int koff = blockIdx.z * kc;
    float* Cz = C ? (C + (size_t)blockIdx.z * M * N) : nullptr;

    const int srow = tid & 127;
    const bool loA = tid < 128;
    const __half* src = loA ? (Ah + (size_t)(bm + srow) * K + koff)
                            : (Bh + (size_t)(bn + srow) * K + koff);
    const uint32_t d0 = (loA ? OF_A0 : OF_B0) + (uint32_t)srow * SA * 2;
    const uint32_t d1 = (loA ? OF_A1 : OF_B1) + (uint32_t)srow * SA * 2;

    const int r  = lane & 7;
    const int q1 = (lane >> 3) & 1;
    const int q2 = lane >> 4;
    const uint32_t oa = (uint32_t)((wm * 64 + q1 * 8 + r) * SA + q2 * 8) * 2;
    const uint32_t ob = (uint32_t)((wn * 32 + q2 * 8 + r) * SA + q1 * 8) * 2;

    float acc[4][4][4];
#pragma unroll
    for (int i = 0; i < 4; i++)
#pragma unroll
        for (int j = 0; j < 4; j++)
#pragma unroll
            for (int t = 0; t < 4; t++) acc[i][j][t] = 0.f;

    const int niter = kc / 64;

    auto load_stage = [&](int j) {
        const uint32_t so = (uint32_t)(j & 1) * STG1S;
        const size_t ko = (size_t)j * 64;
        const __half* s0 = src + ko;
        const uint32_t dd0 = sb + so + d0;
        cpa16(dd0,      s0);      cpa16(dd0 + 16, s0 + 8);
        cpa16(dd0 + 32, s0 + 16); cpa16(dd0 + 48, s0 + 24);
        const __half* s1 = src + ko + 32;
        const uint32_t dd1 = sb + so + d1;
        cpa16(dd1,      s1);      cpa16(dd1 + 16, s1 + 8);
        cpa16(dd1 + 32, s1 + 16); cpa16(dd1 + 48, s1 + 24);
        cpa_commit();
    };

    load_stage(0);

    for (int i = 0; i < niter; i++) {
        asm volatile("cp.async.wait_group 0;" ::: "memory");
        __syncthreads();
        if (i + 1 < niter) load_stage(i + 1);

        const uint32_t so = sb + (uint32_t)(i & 1) * STG1S;
#pragma unroll
        for (int half = 0; half < 2; half++) {
            const uint32_t ofa = so + (half ? OF_A1 : OF_A0);
            const uint32_t ofb = so + (half ? OF_B1 : OF_B0);
#pragma unroll
            for (int ks = 0; ks < 2; ks++) {
                const uint32_t ko = (uint32_t)ks * 32;
                uint32_t ah[4][4], bhf[2][4];
#pragma unroll
                for (int mi = 0; mi < 4; mi++) {
                    const uint32_t aoff = oa + (uint32_t)(mi * 16 * SA) * 2 + ko;
                    ldsm4(ofa + aoff, ah[mi][0], ah[mi][1], ah[mi][2], ah[mi][3]);
                }
#pragma unroll
                for (int p = 0; p < 2; p++) {
                    const uint32_t boff = ob + (uint32_t)(p * 16 * SA) * 2 + ko;
                    ldsm4(ofb + boff, bhf[p][0], bhf[p][1], bhf[p][2], bhf[p][3]);
                }
#pragma unroll
                for (int mi = 0; mi < 4; mi++)
#pragma unroll
                    for (int ni = 0; ni < 4; ni++) {
                        const int p = ni >> 1, e = (ni & 1) * 2;
                        mma16816(acc[mi][ni], ah[mi], bhf[p][e], bhf[p][e + 1]);
                    }
            }
        }
        // no trailing sync: next iter's wait+sync provides WAR ordering
    }

    const int erow = lane >> 2;
    const int ecol = (lane & 3) * 2;
#pragma unroll
    for (int mi = 0; mi < 4; mi++) {
        const int gr = bm + wm * 64 + mi * 16 + erow;
#pragma unroll
        for (int ni = 0; ni < 4; ni++) {
            const int gc = bn + wn * 32 + ni * 8 + ecol;
            float2 v0 = make_float2(acc[mi][ni][0], acc[mi][ni][1]);
            float2 v1 = make_float2(acc[mi][ni][2], acc[mi][ni][3]);
            if (bias) {
                float bx = bias[gc], by = bias[gc + 1];
                v0.x += bx; v0.y += by; v1.x += bx; v1.y += by;
            }
            if (relu) {
                v0.x = fmaxf(v0.x, 0.f); v0.y = fmaxf(v0.y, 0.f);
                v1.x = fmaxf(v1.x, 0.f); v1.y = fmaxf(v1.y, 0.f);
            }
            const size_t o0 = (size_t)gr * N + gc;
            const size_t o1 = (size_t)(gr + 8) * N + gc;
            if (Cz) {
                *(float2*)(Cz + o0) = v0;
                *(float2*)(Cz + o1) = v1;
            }
            if (Ch) {
                *(__half2*)(Ch + o0) = __floats2half2_rn(v0.x, v0.y);
                *(__half2*)(Ch + o1) = __floats2half2_rn(v1.x, v1.y);
            }
        }
    }
}

// ---------------------------------------------------------------------------
// Wide 1-pass fp16 GEMM: 128x256 CTA tile (A staged once per 256-wide strip).
// 256 threads, 8 warps (2M x 4N), warp tile 64x64, BK=32, NST=4, 1 CTA/SM.
// kvmode: B rows remap into stacked per-layer KV blocks of g_wqkvT
//   (stacked row s -> layer s>>10, wqkv row layer*1536 + 512 + (s & 1023)).
// ---------------------------------------------------------------------------
#define NSTW  4
#define STG1  (3 * TILEB)           // A(128 rows) + B(256 rows) = 30720
#define SMEM1 (NSTW * STG1)         // 122880

__global__ void __launch_bounds__(256, 1)
hgemm1_kernel(const __half* __restrict__ Ah, const __half* __restrict__ Bh,
              const float* __restrict__ bias,
              float* __restrict__ C, __half* __restrict__ Ch,
              int M, int N, int K, int relu, int kvmode)
{
    const uint32_t OF_B = TILEB;

    extern __shared__ __half smraw[];
    const uint32_t sb = smem_u32(smraw);

    const int tid  = threadIdx.x;
    const int lane = tid & 31;
    const int wid  = tid >> 5;
    const int wm   = wid >> 2;
    const int wn   = wid & 3;
    const int bm   = blockIdx.y * 128;
    const int bn   = blockIdx.x * 256;

    const int kc   = K / gridDim.z;
    const int koff = blockIdx.z * kc;
    float* Cz = C ? (C + (size_t)blockIdx.z * M * N) : nullptr;

    int brow = bn + tid;
    if (kvmode) {
        const int layer = brow >> 10;
        brow = layer * 1536 + 512 + (brow & 1023);
    }
    const __half* srcB = Bh + (size_t)brow * K + koff;
    const __half* srcA = Ah + (size_t)(bm + (tid & 127)) * K + koff;
    const uint32_t dstB = OF_B + (uint32_t)tid * SA * 2;
    const uint32_t dstA = (uint32_t)(tid & 127) * SA * 2;
    const bool doA = tid < 128;

    const int r  = lane & 7;
    const int q1 = (lane >> 3) & 1;
    const int q2 = lane >> 4;
    const uint32_t oa = (uint32_t)((wm * 64 + q1 * 8 + r) * SA + q2 * 8) * 2;
    const uint32_t ob = (uint32_t)((wn * 64 + q2 * 8 + r) * SA + q1 * 8) * 2;

    float acc[4][8][4];
#pragma unroll
    for (int i = 0; i < 4; i++)
#pragma unroll
        for (int j = 0; j < 8; j++)
#pragma unroll
            for (int t = 0; t < 4; t++) acc[i][j][t] = 0.f;

    const int niter = kc / 32;

    auto load_stage = [&](int j) {
        const uint32_t so = sb + (uint32_t)(j % NSTW) * STG1;
        const size_t ko = (size_t)j * 32;
        const __half* s = srcB + ko;
        const uint32_t d = so + dstB;
        cpa16(d,      s);      cpa16(d + 16, s + 8);
        cpa16(d + 32, s + 16); cpa16(d + 48, s + 24);
        if (doA) {
            const __half* sa = srcA + ko;
            const uint32_t da = so + dstA;
            cpa16(da,      sa);      cpa16(da + 16, sa + 8);
            cpa16(da + 32, sa + 16); cpa16(da + 48, sa + 24);
        }
        cpa_commit();
    };

#pragma unroll
    for (int j = 0; j < NSTW - 1; j++) {
        if (j < niter) load_stage(j);
        else           cpa_commit();
    }

    for (int i = 0; i < niter; i++) {
        asm volatile("cp.async.wait_group %0;" :: "n"(NSTW - 2) : "memory");
        __syncthreads();
        if (i + NSTW - 1 < niter) load_stage(i + NSTW - 1);
        else                      cpa_commit();

        const uint32_t so = sb + (uint32_t)(i % NSTW) * STG1;
#pragma unroll
        for (int ks = 0; ks < 2; ks++) {
            const uint32_t ko = (uint32_t)ks * 32;
            uint32_t ah[4][4], bhf[4][4];
#pragma unroll
            for (int mi = 0; mi < 4; mi++) {
                const uint32_t aoff = oa + (uint32_t)(mi * 16 * SA) * 2 + ko;
                ldsm4(so + aoff, ah[mi][0], ah[mi][1], ah[mi][2], ah[mi][3]);
            }
#pragma unroll
            for (int p = 0; p < 4; p++) {
                const uint32_t boff = ob + (uint32_t)(p * 16 * SA) * 2 + ko;
                ldsm4(so + OF_B + boff, bhf[p][0], bhf[p][1], bhf[p][2], bhf[p][3]);
            }
#pragma unroll
            for (int mi = 0; mi < 4; mi++)
#pragma unroll
                for (int ni = 0; ni < 8; ni++) {
                    const int p = ni >> 1, e = (ni & 1) * 2;
                    mma16816(acc[mi][ni], ah[mi], bhf[p][e], bhf[p][e + 1]);
                }
        }
        // no trailing sync: top-of-next-iter wait+sync provides WAR ordering
    }

    const int erow = lane >> 2;
    const int ecol = (lane & 3) * 2;
#pragma unroll
    for (int mi = 0; mi < 4; mi++) {
        const int gr = bm + wm * 64 + mi * 16 + erow;
#pragma unroll
        for (int ni = 0; ni < 8; ni++) {
            const int gc = bn + wn * 64 + ni * 8 + ecol;
            float2 v0 = make_float2(acc[mi][ni][0], acc[mi][ni][1]);
            float2 v1 = make_float2(acc[mi][ni][2], acc[mi][ni][3]);
            if (bias) {
                float bx = bias[gc], by = bias[gc + 1];
                v0.x += bx; v0.y += by; v1.x += bx; v1.y += by;
            }
            if (relu) {
                v0.x = fmaxf(v0.x, 0.f); v0.y = fmaxf(v0.y, 0.f);
                v1.x = fmaxf(v1.x, 0.f); v1.y = fmaxf(v1.y, 0.f);
            }
            const size_t o0 = (size_t)gr * N + gc;
            const size_t o1 = (size_t)(gr + 8) * N + gc;
            if (Cz) {
                *(float2*)(Cz + o0) = v0;
                *(float2*)(Cz + o1) = v1;
            }
            if (Ch) {
                *(__half2*)(Ch + o0) = __floats2half2_rn(v0.x, v0.y);
                *(__half2*)(Ch + o1) = __floats2half2_rn(v1.x, v1.y);
            }
        }
    }
}

// ---------------------------------------------------------------------------
// 2-pass fp16 GEMM (A = hi+lo exact), BK=32, NST=3. Encoder/decoder only.
// ---------------------------------------------------------------------------
#define NST2  3
#define STG2  (3 * TILEB)
#define SMEM2 (NST2 * STG2)         // 92160

__global__ void __launch_bounds__(256, 2)
hgemm2_kernel(const __half* __restrict__ Ah, const __half* __restrict__ Al,
              const __half* __restrict__ Bh,
              const float* __restrict__ bias,
              float* __restrict__ C, __half* __restrict__ Ch, __half* __restrict__ Cl,
              int M, int N, int K, int relu)
{
    const uint32_t OF_A = 0, OF_AL = TILEB, OF_B = 2 * TILEB;

    extern __shared__ __half smraw[];
    const uint32_t sb = smem_u32(smraw);

    const int tid  = threadIdx.x;
    const int lane = tid & 31;
    const int wid  = tid >> 5;
    const int wm   = wid >> 2;
    const int wn   = wid & 3;
    const int bm   = blockIdx.y * 128;
    const int bn   = blockIdx.x * 128;

    const int srow = tid & 127;
    const bool loA = tid < 128;
    const __half* src0 = loA ? (Ah + (size_t)(bm + srow) * K)
                             : (Al + (size_t)(bm + srow) * K);
    const uint32_t dst0 = (loA ? OF_A : OF_AL) + (uint32_t)srow * SA * 2;
    const __half* src1 = loA ? (Bh + (size_t)(bn + srow) * K) : nullptr;
    const uint32_t dst1 = OF_B + (uint32_t)srow * SA * 2;

    const int r  = lane & 7;
    const int q1 = (lane >> 3) & 1;
    const int q2 = lane >> 4;
    const uint32_t oa = (uint32_t)((wm * 64 + q1 * 8 + r) * SA + q2 * 8) * 2;
    const uint32_t ob = (uint32_t)((wn * 32 + q2 * 8 + r) * SA + q1 * 8) * 2;

    float acc[4][4][4];
#pragma unroll
    for (int i = 0; i < 4; i++)
#pragma unroll
        for (int j = 0; j < 4; j++)
#pragma unroll
            for (int t = 0; t < 4; t++) acc[i][j][t] = 0.f;

    const int niter = K / 32;

    auto load_stage = [&](int j) {
        const uint32_t so = (uint32_t)(j % NST2) * STG2;
        const size_t ko = (size_t)j * 32;
        const __half* s = src0 + ko;
        const uint32_t d = sb + so + dst0;
        cpa16(d,      s);
        cpa16(d + 16, s + 8);
        cpa16(d + 32, s + 16);
        cpa16(d + 48, s + 24);
        if (loA) {
            const __half* s1 = src1 + ko;
            const uint32_t d1 = sb + so + dst1;
            cpa16(d1,      s1);
            cpa16(d1 + 16, s1 + 8);
            cpa16(d1 + 32, s1 + 16);
            cpa16(d1 + 48, s1 + 24);
        }
        cpa_commit();
    };

#pragma unroll
    for (int j = 0; j < NST2 - 1; j++) {
        if (j < niter) load_stage(j);
        else           cpa_commit();
    }

    for (int i = 0; i < niter; i++) {
        asm volatile("cp.async.wait_group 1;" ::: "memory");
        __syncthreads();
        if (i + NST2 - 1 < niter) load_stage(i + NST2 - 1);
        else                      cpa_commit();

        const uint32_t so = sb + (uint32_t)(i % NST2) * STG2;
#pragma unroll
        for (int ks = 0; ks < 2; ks++) {
            const uint32_t ko = (uint32_t)ks * 32;
            uint32_t ah[4][4], al[4][4], bhf[2][4];
#pragma unroll
            for (int mi = 0; mi < 4; mi++) {
                const uint32_t aoff = oa + (uint32_t)(mi * 16 * SA) * 2 + ko;
                ldsm4(so + OF_A + aoff,  ah[mi][0], ah[mi][1], ah[mi][2], ah[mi][3]);
                ldsm4(so + OF_AL + aoff, al[mi][0], al[mi][1], al[mi][2], al[mi][3]);
            }
#pragma unroll
            for (int p = 0; p < 2; p++) {
                const uint32_t boff = ob + (uint32_t)(p * 16 * SA) * 2 + ko;
                ldsm4(so + OF_B + boff, bhf[p][0], bhf[p][1], bhf[p][2], bhf[p][3]);
            }
#pragma unroll
            for (int mi = 0; mi < 4; mi++)
#pragma unroll
                for (int ni = 0; ni < 4; ni++) {
                    const int p = ni >> 1, e = (ni & 1) * 2;
                    mma16816(acc[mi][ni], ah[mi], bhf[p][e], bhf[p][e + 1]);
                }
#pragma unroll
            for (int mi = 0; mi < 4; mi++)
#pragma unroll
                for (int ni = 0; ni < 4; ni++) {
                    const int p = ni >> 1, e = (ni & 1) * 2;
                    mma16816(acc[mi][ni], al[mi], bhf[p][e], bhf[p][e + 1]);
                }
        }
    }

    const int erow = lane >> 2;
    const int ecol = (lane & 3) * 2;
#pragma unroll
    for (int mi = 0; mi < 4; mi++) {
        const int gr = bm + wm * 64 + mi * 16 + erow;
#pragma unroll
        for (int ni = 0; ni < 4; ni++) {
            const int gc = bn + wn * 32 + ni * 8 + ecol;
            float2 v0 = make_float2(acc[mi][ni][0], acc[mi][ni][1]);
            float2 v1 = make_float2(acc[mi][ni][2], acc[mi][ni][3]);
            if (bias) {
                float bx = bias[gc], by = bias[gc + 1];
                v0.x += bx; v0.y += by; v1.x += bx; v1.y += by;
            }
            if (relu) {
                v0.x = fmaxf(v0.x, 0.f); v0.y = fmaxf(v0.y, 0.f);
                v1.x = fmaxf(v1.x, 0.f); v1.y = fmaxf(v1.y, 0.f);
            }
            const size_t o0 = (size_t)gr * N + gc;
            const size_t o1 = (size_t)(gr + 8) * N + gc;
            if (C) {
                *(float2*)(C + o0) = v0;
                *(float2*)(C + o1) = v1;
            }
            if (Ch) {
                __half2 h0, l0, h1, l1;
                split2(v0.x, v0.y, h0, l0);
                split2(v1.x, v1.y, h1, l1);
                *(__half2*)(Ch + o0) = h0;
                *(__half2*)(Ch + o1) = h1;
                if (Cl) {
                    *(__half2*)(Cl + o0) = l0;
                    *(__half2*)(Cl + o1) = l1;
                }
            }
        }
    }
}

// ---------------------------------------------------------------------------
// Weight transpose + fp16 convert
// ---------------------------------------------------------------------------
__global__ void wconv_kernel(const float* __restrict__ W,
                             __half* __restrict__ Th,
                             int K, int N,
                             size_t inLS, size_t outLS, int rowOff)
{
    __shared__ float t[32][33];
    const float* Wz = W + (size_t)blockIdx.z * inLS;
    __half* Thz = Th + (size_t)blockIdx.z * outLS;
    const int n0 = blockIdx.x * 32, k0 = blockIdx.y * 32;
    const int tx = threadIdx.x, ty = threadIdx.y;
#pragma unroll
    for (int i = 0; i < 32; i += 8)
        t[ty + i][tx] = (n0 + tx < N) ? Wz[(size_t)(k0 + ty + i) * N + n0 + tx] : 0.f;
    __syncthreads();
#pragma unroll
    for (int i = 0; i < 32; i += 8) {
        float f = t[tx][ty + i];
        Thz[(size_t)(rowOff + n0 + ty + i) * K + k0 + tx] = __float2half_rn(f);
    }
}

// Fused Wq/Wk/Wv + Wenc transpose: grid.x covers 3*16 (qkv) + 16 (wenc).
__global__ void wconv4_kernel(const float* __restrict__ Wq,
                              const float* __restrict__ Wk,
                              const float* __restrict__ Wv,
                              const float* __restrict__ Wenc,
                              __half* __restrict__ Tqkv,
                              __half* __restrict__ Tenc)
{
    __shared__ float t[32][33];
    const int nb  = DD / 32;                 // 16
    const int mat = blockIdx.x / nb;         // 0..3
    const int n0  = (blockIdx.x - mat * nb) * 32;
    const int k0  = blockIdx.y * 32;
    const int tx = threadIdx.x, ty = threadIdx.y;

    if (mat < 3) {
        const float* W = (mat == 0 ? Wq : (mat == 1 ? Wk : Wv))
                         + (size_t)blockIdx.z * DD * DD;
        __half* Thz = Tqkv + (size_t)blockIdx.z * 3 * DD * DD + (size_t)mat * DD * DD;
#pragma unroll
        for (int i = 0; i < 32; i += 8)
            t[ty + i][tx] = W[(size_t)(k0 + ty + i) * DD + n0 + tx];
        __syncthreads();
#pragma unroll
        for (int i = 0; i < 32; i += 8)
            Thz[(size_t)(n0 + ty + i) * DD + k0 + tx] = __float2half_rn(t[tx][ty + i]);
    } else {
        if (blockIdx.z != 0 || k0 >= KENC) return;
#pragma unroll
        for (int i = 0; i < 32; i += 8)
            t[ty + i][tx] = Wenc[(size_t)(k0 + ty + i) * DD + n0 + tx];
        __syncthreads();
#pragma unroll
        for (int i = 0; i < 32; i += 8)
            Tenc[(size_t)(n0 + ty + i) * KENC + k0 + tx] = __float2half_rn(t[tx][ty + i]);
    }
}

// ---------------------------------------------------------------------------
// Concat positional encoding + fp16 hi/lo split
// ---------------------------------------------------------------------------
__global__ void concat_pe_split(const float* __restrict__ x,
                                __half* __restrict__ xh, __half* __restrict__ xl)
{
    int idx = blockIdx.x * 256 + threadIdx.x;
    if (idx >= MROWS * KENC) return;
    int row = idx >> 7;
    int c   = idx & 127;
    float val;
    if (c < EE) val = x[(size_t)row * EE + c];
    else        val = (float)(row % NN) * (1.f / (float)(NN - 1));
    __half h = __float2half_rn(val);
    xh[idx] = h;
    xl[idx] = __float2half_rn(val - __half2float(h));
}

// ---------------------------------------------------------------------------
// Decoder strip copy
// ---------------------------------------------------------------------------
__global__ void dec_copy_kernel(const float* __restrict__ dec,
                                const float* __restrict__ bias,
                                float* __restrict__ out)
{
    int idx = blockIdx.x * 256 + threadIdx.x;
    if (idx >= MROWS * EE) return;
    int row = idx / EE;
    int c   = idx - row * EE;
    out[idx] = dec[(size_t)row * 128 + c] + bias[c];
}

// ---------------------------------------------------------------------------
// Batched diagonal-softmax attention: one block per (h, b).
// ---------------------------------------------------------------------------
__global__ void __launch_bounds__(256)
batt_kernel(const float* __restrict__ q, const float* __restrict__ q2, int ldq,
            const float* __restrict__ k, int ldk,
            const float* __restrict__ v, int ldv,
            __half* __restrict__ oh, int masked)
{
    __shared__ float kT[64][160];   // [d][m], cols 144..159 zeroed

    const int h = blockIdx.x, b = blockIdx.y;
    const int tid  = threadIdx.x;
    const int lane = tid & 31;
    const int w    = tid >> 5;      // 0..7
    const int hoff = h * DK;
    const int rb   = b * NN;

    for (int idx = tid; idx < 64 * 16; idx += 256)
        kT[idx >> 4][144 + (idx & 15)] = 0.f;
    for (int idx = tid; idx < NN * 16; idx += 256) {
        const int m = idx >> 4, c = (idx & 15) * 4;
        const float4 kv = *(const float4*)(k + (size_t)(rb + m) * ldk + hoff + c);
        kT[c + 0][m] = kv.x;
        kT[c + 1][m] = kv.y;
        kT[c + 2][m] = kv.z;
        kT[c + 3][m] = kv.w;
    }
    __syncthreads();

    for (int n = w; n < NN; n += 8) {
        const int row = rb + n;
        float q0 = q[(size_t)row * ldq + hoff + lane];
        float q1 = q[(size_t)row * ldq + hoff + 32 + lane];
        if (q2) {
            q0 += q2[(size_t)row * ldq + hoff + lane];
            q1 += q2[(size_t)row * ldq + hoff + 32 + lane];
        }

        float s0 = 0.f, s1 = 0.f, s2 = 0.f, s3 = 0.f, s4 = 0.f;
#pragma unroll
        for (int d = 0; d < 32; d++) {
            const float qd = __shfl_sync(0xffffffffu, q0, d);
            s0 += qd * kT[d][lane];
            s1 += qd * kT[d][lane + 32];
            s2 += qd * kT[d][lane + 64];
            s3 += qd * kT[d][lane + 96];
            s4 += qd * kT[d][lane + 128];
        }
#pragma unroll
        for (int d = 0; d < 32; d++) {
            const float qd = __shfl_sync(0xffffffffu, q1, d);
            s0 += qd * kT[32 + d][lane];
            s1 += qd * kT[32 + d][lane + 32];
            s2 += qd * kT[32 + d][lane + 64];
            s3 += qd * kT[32 + d][lane + 96];
            s4 += qd * kT[32 + d][lane + 128];
        }

        float tmp = (n < 32) ? s0 : (n < 64) ? s1 : (n < 96) ? s2
                  : (n < 128) ? s3 : s4;
        const float sd = __shfl_sync(0xffffffffu, tmp, n & 31);

        const int mlim = masked ? (n + 1) : NN;
        if (lane       >= mlim) s0 = -3.0e38f;
        if (lane + 32  >= mlim) s1 = -3.0e38f;
        if (lane + 64  >= mlim) s2 = -3.0e38f;
        if (lane + 96  >= mlim) s3 = -3.0e38f;
        if (lane + 128 >= mlim) s4 = -3.0e38f;

        float mx = fmaxf(fmaxf(fmaxf(s0, s1), fmaxf(s2, s3)), s4);
#pragma unroll
        for (int o = 16; o; o >>= 1) mx = fmaxf(mx, __shfl_xor_sync(0xffffffffu, mx, o));

        float e = expf(s0 - mx) + expf(s1 - mx) + expf(s2 - mx)
                + expf(s3 - mx) + expf(s4 - mx);
#pragma unroll
        for (int o = 16; o; o >>= 1) e += __shfl_xor_sync(0xffffffffu, e, o);

        const float dcoef = expf(sd - mx) / e;

        const float2 vv = *(const float2*)(v + (size_t)row * ldv + hoff + lane * 2);
        *(__half2*)(oh + (size_t)row * DD + hoff + lane * 2) =
            __floats2half2_rn(dcoef * vv.x, dcoef * vv.y);
    }
}

// ---------------------------------------------------------------------------
// Fused residual add + LayerNorm (D=512), shuffle reductions.
// ---------------------------------------------------------------------------
__global__ void __launch_bounds__(256)
add_ln_kernel(const float* __restrict__ a, const float* __restrict__ a2,
              const float* __restrict__ bias,
              const float* __restrict__ r,
              const float* __restrict__ g, const float* __restrict__ beta,
              float* __restrict__ out,
              __half* __restrict__ oh, __half* __restrict__ ol)
{
    const int row = blockIdx.x;
    const int t = threadIdx.x;
    __shared__ float red1[8];
    __shared__ float red2[8];

    const size_t base = (size_t)row * DD;
    float x0 = a[base + t]       + r[base + t];
    float x1 = a[base + 256 + t] + r[base + 256 + t];
    if (a2)   { x0 += a2[base + t]; x1 += a2[base + 256 + t]; }
    if (bias) { x0 += bias[t];      x1 += bias[256 + t]; }

    float s = x0 + x1;
#pragma unroll
    for (int o = 16; o; o >>= 1) s += __shfl_xor_sync(0xffffffffu, s, o);
    if ((t & 31) == 0) red1[t >> 5] = s;
    __syncthreads();
    const float mean = (red1[0] + red1[1] + red1[2] + red1[3] +
                        red1[4] + red1[5] + red1[6] + red1[7]) * (1.f / (float)DD);

    const float d0 = x0 - mean, d1 = x1 - mean;
    float vv = d0 * d0 + d1 * d1;
#pragma unroll
    for (int o = 16; o; o >>= 1) vv += __shfl_xor_sync(0xffffffffu, vv, o);
    if ((t & 31) == 0) red2[t >> 5] = vv;
    __syncthreads();
    const float var = (red2[0] + red2[1] + red2[2] + red2[3] +
                       red2[4] + red2[5] + red2[6] + red2[7]) * (1.f / (float)DD);
    const float inv = rsqrtf(var + 1e-5f);

    const float y0 = d0 * inv * g[t]       + beta[t];
    const float y1 = d1 * inv * g[256 + t] + beta[256 + t];
    if (out) {
        out[base + t]       = y0;
        out[base + 256 + t] = y1;
    }
    if (oh) {
        __half h0 = __float2half_rn(y0);
        __half h1 = __float2half_rn(y1);
        oh[base + t]       = h0;
        oh[base + 256 + t] = h1;
        if (ol) {
            ol[base + t]       = __float2half_rn(y0 - __half2float(h0));
            ol[base + 256 + t] = __float2half_rn(y1 - __half2float(h1));
        }
    }
}

// ---------------------------------------------------------------------------
// Host orchestration
// ---------------------------------------------------------------------------
static inline void hgemm1s(const __half* Ah, const __half* Bh,
                           const float* bias, float* C, __half* Ch,
                           int M, int N, int K, int relu)
{
    dim3 grid(N / 128, M / 128, 1);
    hgemm1s_kernel<<<grid, 256, SMEM1S>>>(Ah, Bh, bias, C, Ch, M, N, K, relu);
}

static inline void hgemm1(const __half* Ah, const __half* Bh,
                          const float* bias, float* C, __half* Ch,
                          int M, int N, int K, int relu, int splitk = 1, int kvmode = 0)
{
    dim3 grid(N / 256, M / 128, splitk);
    hgemm1_kernel<<<grid, 256, SMEM1>>>(Ah, Bh, bias, C, Ch, M, N, K, relu, kvmode);
}

static inline void hgemm2(const __half* Ah, const __half* Al, const __half* Bh,
                          const float* bias, float* C, __half* Ch, __half* Cl,
                          int M, int N, int K, int relu)
{
    dim3 grid(N / 128, M / 128, 1);
    hgemm2_kernel<<<grid, 256, SMEM2>>>(Ah, Al, Bh, bias, C, Ch, Cl, M, N, K, relu);
}

extern "C" void kernel_launch(void* const* d_in, const int* in_sizes, int n_in,
                              void* d_out, int out_size)
{
    const float* x    = (const float*)d_in[1];
    const float* Wenc = (const float*)d_in[3];
    const float* benc = (const float*)d_in[4];
    const float* Wq   = (const float*)d_in[5];
    const float* Wk   = (const float*)d_in[6];
    const float* Wv   = (const float*)d_in[7];
    const float* Wo   = (const float*)d_in[8];
    const float* bo   = (const float*)d_in[9];
    const float* ln1g = (const float*)d_in[10];
    const float* ln1b = (const float*)d_in[11];
    const float* ln2g = (const float*)d_in[12];
    const float* ln2b = (const float*)d_in[13];
    const float* ln3g = (const float*)d_in[14];
    const float* ln3b = (const float*)d_in[15];
    const float* W1   = (const float*)d_in[16];
    const float* b1   = (const float*)d_in[17];
    const float* W2   = (const float*)d_in[18];
    const float* b2   = (const float*)d_in[19];
    const float* Wdec = (const float*)d_in[20];
    const float* bdec = (const float*)d_in[21];

    float *p_xe, *p_qkv, *p_kv4, *p_a2, *p_ao, *p_part, *p_dec;
    cudaGetSymbolAddress((void**)&p_xe,   g_xe);
    cudaGetSymbolAddress((void**)&p_qkv,  g_qkv);
    cudaGetSymbolAddress((void**)&p_kv4,  g_kv4);
    cudaGetSymbolAddress((void**)&p_a2,   g_a2);
    cudaGetSymbolAddress((void**)&p_ao,   g_ao);
    cudaGetSymbolAddress((void**)&p_part, g_part);
    cudaGetSymbolAddress((void**)&p_dec,  g_dec);

    __half *xp_h, *xp_l, *xe_h, *cur_h, *cur_l, *qln_h, *at_h, *a2_h, *ao_h, *hid_h;
    cudaGetSymbolAddress((void**)&xp_h,  g_xp_h);
    cudaGetSymbolAddress((void**)&xp_l,  g_xp_l);
    cudaGetSymbolAddress((void**)&xe_h,  g_xe_h);
    cudaGetSymbolAddress((void**)&cur_h, g_cur_h);
    cudaGetSymbolAddress((void**)&cur_l, g_cur_l);
    cudaGetSymbolAddress((void**)&qln_h, g_qln_h);
    cudaGetSymbolAddress((void**)&at_h,  g_at_h);
    cudaGetSymbolAddress((void**)&a2_h,  g_a2_h);
    cudaGetSymbolAddress((void**)&ao_h,  g_ao_h);
    cudaGetSymbolAddress((void**)&hid_h, g_hid_h);

    __half *wqkv, *wo, *w1, *w2, *wenc, *wdec;
    cudaGetSymbolAddress((void**)&wqkv, g_wqkvT);
    cudaGetSymbolAddress((void**)&wo,   g_woT);
    cudaGetSymbolAddress((void**)&w1,   g_w1T);
    cudaGetSymbolAddress((void**)&w2,   g_w2T);
    cudaGetSymbolAddress((void**)&wenc, g_wencT);
    cudaGetSymbolAddress((void**)&wdec, g_wdecT);

    cudaFuncSetAttribute((const void*)hgemm1s_kernel,
                         cudaFuncAttributeMaxDynamicSharedMemorySize, SMEM1S);
    cudaFuncSetAttribute((const void*)hgemm1_kernel,
                         cudaFuncAttributeMaxDynamicSharedMemorySize, SMEM1);
    cudaFuncSetAttribute((const void*)hgemm2_kernel,
                         cudaFuncAttributeMaxDynamicSharedMemorySize, SMEM2);

    dim3 wb(32, 8);
    const size_t dd2 = (size_t)DD * DD;
    const size_t df  = (size_t)DD * FF;
    dim3 batt_grid(HH, BB);
    float* part1 = p_part + (size_t)MROWS * DD;

    // [1] fused QKV + Wenc weight conversion
    wconv4_kernel<<<dim3(4 * (DD/32), DD/32, LL), wb>>>(Wq, Wk, Wv, Wenc, wqkv, wenc);
    // [2] input concat+split
    concat_pe_split<<<(MROWS * KENC + 255) / 256, 256>>>(x, xp_h, xp_l);
    // [3] encoder GEMM (2-pass)
    hgemm2(xp_h, xp_l, wenc, benc, p_xe, xe_h, nullptr, MROWS, DD, KENC, 0);
    // [4] layer-0 QKV GEMM  <-- ncu capture target
    hgemm1s(xe_h, wqkv, nullptr, p_qkv, nullptr, MROWS, 3 * DD, DD, 0);
    // [5] ALL layers' MHA2 K/V projections in one wide GEMM (xe-only dependent)
    hgemm1(xe_h, wqkv, nullptr, p_kv4, nullptr, MROWS, 4 * 1024, DD, 0, 1, 1);
    // [6..9] remaining weights
    wconv_kernel<<<dim3(DD/32, DD/32, LL), wb>>>(Wo, wo, DD, DD, dd2, dd2, 0);
    wconv_kernel<<<dim3(FF/32, DD/32, LL), wb>>>(W1, w1, DD, FF, df, df, 0);
    wconv_kernel<<<dim3(DD/32, FF/32, LL), wb>>>(W2, w2, FF, DD, df, df, 0);
    wconv_kernel<<<dim3(4, DD/32, 1), wb>>>(Wdec, wdec, DD, EE, 0, 0, 0);

    for (int l = 0; l < LL; l++) {
        const __half* in_h = (l == 0) ? xe_h : cur_h;
        const __half* wqkv_l = wqkv + (size_t)l * 3 * DD * DD;
        const __half* wo_l   = wo + (size_t)l * DD * DD;
        const __half* w1_l   = w1 + (size_t)l * DD * FF;
        const __half* w2_l   = w2 + (size_t)l * DD * FF;
        const float* bol = bo + (size_t)l * DD;
        const float* b1l = b1 + (size_t)l * FF;
        const float* b2l = b2 + (size_t)l * DD;
        const float* kv_l = p_kv4 + (size_t)l * 1024;   // k cols [0,512), v cols [512,1024)

        // --- MHA1 (causal): fused QKV (layer 0's already launched) ---
        if (l > 0)
            hgemm1s(in_h, wqkv_l, nullptr, p_qkv, nullptr, MROWS, 3 * DD, DD, 0);
        batt_kernel<<<batt_grid, 256>>>(p_qkv, nullptr, 3 * DD,
                                        p_qkv + DD, 3 * DD,
                                        p_qkv + 2 * DD, 3 * DD, at_h, 1);
        hgemm1s(at_h, wo_l, bol, p_part, nullptr, MROWS, DD, DD, 0);
        add_ln_kernel<<<MROWS, 256>>>(p_part, nullptr, nullptr, p_xe,
                                      ln1g + (size_t)l * DD, ln1b + (size_t)l * DD,
                                      nullptr, qln_h, nullptr);

        // --- MHA2 (no mask): Q projection; K/V from precomputed kv4 ---
        hgemm1s(qln_h, wqkv_l, nullptr, p_part, nullptr, MROWS, DD, DD, 0);
        batt_kernel<<<batt_grid, 256>>>(p_part, nullptr, DD,
                                        kv_l, 4 * 1024,
                                        kv_l + DD, 4 * 1024, at_h, 0);
        hgemm1s(at_h, wo_l, bol, p_a2, a2_h, MROWS, DD, DD, 0);

        // --- FF stack 1 (wide tiles; W2 split-K=2 combined in add_ln) ---
        hgemm1(a2_h, w1_l, b1l, nullptr, hid_h, MROWS, FF, DD, 1);
        hgemm1(hid_h, w2_l, nullptr, p_part, nullptr, MROWS, DD, FF, 0, 2);
        add_ln_kernel<<<MROWS, 256>>>(p_part, part1, b2l, p_a2,
                                      ln2g + (size_t)l * DD, ln2b + (size_t)l * DD,
                                      p_ao, ao_h, nullptr);

        // --- FF stack 2 ---
        hgemm1(ao_h, w1_l, b1l, nullptr, hid_h, MROWS, FF, DD, 1);
        hgemm1(hid_h, w2_l, nullptr, p_part, nullptr, MROWS, DD, FF, 0, 2);
        add_ln_kernel<<<MROWS, 256>>>(p_part, part1, b2l, p_ao,
                                      ln3g + (size_t)l * DD, ln3b + (size_t)l * DD,
                                      nullptr, cur_h, cur_l);
    }

    // --- Decoder (2-pass, padded N=128) ---
    hgemm2(cur_h, cur_l, wdec, nullptr, p_dec, nullptr, nullptr, MROWS, 128, DD, 0);
    dec_copy_kernel<<<(MROWS * EE + 255) / 256, 256>>>(p_dec, bdec, (float*)d_out);
}

// round 17
// speedup vs baseline: 1.0775x; 1.0775x over previous
#include <cuda_runtime.h>
#include <cuda_fp16.h>
#include <cstdint>
#include <cstddef>

// ---------------------------------------------------------------------------
// Problem constants
// ---------------------------------------------------------------------------
#define BB   32
#define NN   144
#define EE   127
#define DD   512
#define HH   8
#define DK   64
#define DV   64
#define FF   16384
#define LL   4
#define MROWS (BB*NN)        // 4608
#define KENC  (EE+1)         // 128

// ---------------------------------------------------------------------------
// Scratch (static device globals)
// ---------------------------------------------------------------------------
__device__ float g_xe  [MROWS * DD];
__device__ float g_qkv [MROWS * 3 * DD];
__device__ float g_kv4 [(size_t)MROWS * 4 * 1024];   // all-layer KV
__device__ float g_a2  [MROWS * DD];
__device__ float g_ao  [MROWS * DD];
__device__ float g_part[2 * MROWS * DD];
__device__ float g_dec [MROWS * 128];

// fp16 activations
__device__ __half g_xp_h [MROWS * KENC], g_xp_l [MROWS * KENC];
__device__ __half g_xe_h [MROWS * DD];
__device__ __half g_cur_h[MROWS * DD], g_cur_l[MROWS * DD];
__device__ __half g_qln_h[MROWS * DD];
__device__ __half g_at_h [MROWS * DD];
__device__ __half g_a2_h [MROWS * DD];
__device__ __half g_ao_h [MROWS * DD];
__device__ __half g_hid_h[(size_t)MROWS * FF];

// Transposed fp16 weights, [Nrows, K] row-major per layer.
__device__ __half g_wqkvT[(size_t)LL * 3 * DD * DD];
__device__ __half g_woT  [(size_t)LL * DD * DD];
__device__ __half g_w1T  [(size_t)LL * FF * DD];
__device__ __half g_w2T  [(size_t)LL * DD * FF];
__device__ __half g_wencT[DD * KENC];
__device__ __half g_wdecT[128 * DD];

// ---------------------------------------------------------------------------
// Small helpers
// ---------------------------------------------------------------------------
__device__ __forceinline__ uint32_t smem_u32(const void* p) {
    uint32_t a;
    asm("{ .reg .u64 t; cvta.to.shared.u64 t, %1; cvt.u32.u64 %0, t; }" : "=r"(a) : "l"(p));
    return a;
}
__device__ __forceinline__ void cpa16(uint32_t d, const void* s) {
    asm volatile("cp.async.cg.shared.global [%0], [%1], 16;" :: "r"(d), "l"(s));
}
__device__ __forceinline__ void cpa_commit() {
    asm volatile("cp.async.commit_group;" ::: "memory");
}
__device__ __forceinline__ void ldsm4(uint32_t a, uint32_t& r0, uint32_t& r1,
                                      uint32_t& r2, uint32_t& r3) {
    asm volatile("ldmatrix.sync.aligned.m8n8.x4.shared.b16 {%0,%1,%2,%3}, [%4];"
                 : "=r"(r0), "=r"(r1), "=r"(r2), "=r"(r3) : "r"(a));
}
__device__ __forceinline__ void mma16816(float* c, const uint32_t* a,
                                         uint32_t b0, uint32_t b1) {
    asm volatile("mma.sync.aligned.m16n8k16.row.col.f32.f16.f16.f32 "
                 "{%0,%1,%2,%3},{%4,%5,%6,%7},{%8,%9},{%0,%1,%2,%3};"
                 : "+f"(c[0]), "+f"(c[1]), "+f"(c[2]), "+f"(c[3])
                 : "r"(a[0]), "r"(a[1]), "r"(a[2]), "r"(a[3]), "r"(b0), "r"(b1));
}
__device__ __forceinline__ void split2(float x, float y, __half2& h, __half2& l) {
    __half hx = __float2half_rn(x);
    __half hy = __float2half_rn(y);
    h = __halves2half2(hx, hy);
    l = __halves2half2(__float2half_rn(x - __half2float(hx)),
                       __float2half_rn(y - __half2float(hy)));
}

#define SA    40
#define TILEB (128 * SA * 2)        // 10240 bytes

// ---------------------------------------------------------------------------
// Small-N 1-pass fp16 GEMM: 128x128 CTA tile, 256 threads, 8 warps (2M x 4N),
// warp tile 64x32, BK=64, NST=2, 2 CTAs/SM. Split-K via gridDim.z.
// ---------------------------------------------------------------------------
#define STG1S  (4 * TILEB)          // A0,A1,B0,B1 = 40960
#define SMEM1S (2 * STG1S)          // 81920

__global__ void __launch_bounds__(256, 2)
hgemm1s_kernel(const __half* __restrict__ Ah, const __half* __restrict__ Bh,
               const float* __restrict__ bias,
               float* __restrict__ C, __half* __restrict__ Ch,
               int M, int N, int K, int relu)
{
    const uint32_t OF_A0 = 0, OF_A1 = TILEB, OF_B0 = 2 * TILEB, OF_B1 = 3 * TILEB;

    extern __shared__ __half smraw[];
    const uint32_t sb = smem_u32(smraw);

    const int tid  = threadIdx.x;
    const int lane = tid & 31;
    const int wid  = tid >> 5;
    const int wm   = wid >> 2;
    const int wn   = wid & 3;
    const int bm   = blockIdx.y * 128;
    const int bn   = blockIdx.x * 128;

    const int kc   = K / gridDim.z;
    const int koff = blockIdx.z * kc;
    float* Cz = C ? (C + (size_t)blockIdx.z * M * N) : nullptr;

    const int srow = tid & 127;
    const bool loA = tid < 128;
    const __half* src = loA ? (Ah + (size_t)(bm + srow) * K + koff)
                            : (Bh + (size_t)(bn + srow) * K + koff);
    const uint32_t d0 = (loA ? OF_A0 : OF_B0) + (uint32_t)srow * SA * 2;
    const uint32_t d1 = (loA ? OF_A1 : OF_B1) + (uint32_t)srow * SA * 2;

    const int r  = lane & 7;
    const int q1 = (lane >> 3) & 1;
    const int q2 = lane >> 4;
    const uint32_t oa = (uint32_t)((wm * 64 + q1 * 8 + r) * SA + q2 * 8) * 2;
    const uint32_t ob = (uint32_t)((wn * 32 + q2 * 8 + r) * SA + q1 * 8) * 2;

    float acc[4][4][4];
#pragma unroll
    for (int i = 0; i < 4; i++)
#pragma unroll
        for (int j = 0; j < 4; j++)
#pragma unroll
            for (int t = 0; t < 4; t++) acc[i][j][t] = 0.f;

    const int niter = kc / 64;

    auto load_stage = [&](int j) {
        const uint32_t so = (uint32_t)(j & 1) * STG1S;
        const size_t ko = (size_t)j * 64;
        const __half* s0 = src + ko;
        const uint32_t dd0 = sb + so + d0;
        cpa16(dd0,      s0);      cpa16(dd0 + 16, s0 + 8);
        cpa16(dd0 + 32, s0 + 16); cpa16(dd0 + 48, s0 + 24);
        const __half* s1 = src + ko + 32;
        const uint32_t dd1 = sb + so + d1;
        cpa16(dd1,      s1);      cpa16(dd1 + 16, s1 + 8);
        cpa16(dd1 + 32, s1 + 16); cpa16(dd1 + 48, s1 + 24);
        cpa_commit();
    };

    load_stage(0);

    for (int i = 0; i < niter; i++) {
        asm volatile("cp.async.wait_group 0;" ::: "memory");
        __syncthreads();
        if (i + 1 < niter) load_stage(i + 1);

        const uint32_t so = sb + (uint32_t)(i & 1) * STG1S;
#pragma unroll
        for (int half = 0; half < 2; half++) {
            const uint32_t ofa = so + (half ? OF_A1 : OF_A0);
            const uint32_t ofb = so + (half ? OF_B1 : OF_B0);
#pragma unroll
            for (int ks = 0; ks < 2; ks++) {
                const uint32_t ko = (uint32_t)ks * 32;
                uint32_t ah[4][4], bhf[2][4];
#pragma unroll
                for (int mi = 0; mi < 4; mi++) {
                    const uint32_t aoff = oa + (uint32_t)(mi * 16 * SA) * 2 + ko;
                    ldsm4(ofa + aoff, ah[mi][0], ah[mi][1], ah[mi][2], ah[mi][3]);
                }
#pragma unroll
                for (int p = 0; p < 2; p++) {
                    const uint32_t boff = ob + (uint32_t)(p * 16 * SA) * 2 + ko;
                    ldsm4(ofb + boff, bhf[p][0], bhf[p][1], bhf[p][2], bhf[p][3]);
                }
#pragma unroll
                for (int mi = 0; mi < 4; mi++)
#pragma unroll
                    for (int ni = 0; ni < 4; ni++) {
                        const int p = ni >> 1, e = (ni & 1) * 2;
                        mma16816(acc[mi][ni], ah[mi], bhf[p][e], bhf[p][e + 1]);
                    }
            }
        }
        // no trailing sync: next iter's wait+sync provides WAR ordering
    }

    const int erow = lane >> 2;
    const int ecol = (lane & 3) * 2;
#pragma unroll
    for (int mi = 0; mi < 4; mi++) {
        const int gr = bm + wm * 64 + mi * 16 + erow;
#pragma unroll
        for (int ni = 0; ni < 4; ni++) {
            const int gc = bn + wn * 32 + ni * 8 + ecol;
            float2 v0 = make_float2(acc[mi][ni][0], acc[mi][ni][1]);
            float2 v1 = make_float2(acc[mi][ni][2], acc[mi][ni][3]);
            if (bias) {
                float bx = bias[gc], by = bias[gc + 1];
                v0.x += bx; v0.y += by; v1.x += bx; v1.y += by;
            }
            if (relu) {
                v0.x = fmaxf(v0.x, 0.f); v0.y = fmaxf(v0.y, 0.f);
                v1.x = fmaxf(v1.x, 0.f); v1.y = fmaxf(v1.y, 0.f);
            }
            const size_t o0 = (size_t)gr * N + gc;
            const size_t o1 = (size_t)(gr + 8) * N + gc;
            if (Cz) {
                *(float2*)(Cz + o0) = v0;
                *(float2*)(Cz + o1) = v1;
            }
            if (Ch) {
                *(__half2*)(Ch + o0) = __floats2half2_rn(v0.x, v0.y);
                *(__half2*)(Ch + o1) = __floats2half2_rn(v1.x, v1.y);
            }
        }
    }
}

// ---------------------------------------------------------------------------
// Wide 1-pass fp16 GEMM: 128x256 CTA tile (A staged once per 256-wide strip).
// 256 threads, 8 warps (2M x 4N), warp tile 64x64, BK=32, NST=3, 1 CTA/SM.
// kvmode: B rows remap into stacked per-layer KV blocks of g_wqkvT.
// ---------------------------------------------------------------------------
#define STG1  (3 * TILEB)           // A(128 rows) + B(256 rows) = 30720
#define SMEM1 (3 * STG1)            // 92160

__global__ void __launch_bounds__(256, 1)
hgemm1_kernel(const __half* __restrict__ Ah, const __half* __restrict__ Bh,
              const float* __restrict__ bias,
              float* __restrict__ C, __half* __restrict__ Ch,
              int M, int N, int K, int relu, int kvmode)
{
    const uint32_t OF_B = TILEB;

    extern __shared__ __half smraw[];
    const uint32_t sb = smem_u32(smraw);

    const int tid  = threadIdx.x;
    const int lane = tid & 31;
    const int wid  = tid >> 5;
    const int wm   = wid >> 2;
    const int wn   = wid & 3;
    const int bm   = blockIdx.y * 128;
    const int bn   = blockIdx.x * 256;

    const int kc   = K / gridDim.z;
    const int koff = blockIdx.z * kc;
    float* Cz = C ? (C + (size_t)blockIdx.z * M * N) : nullptr;

    int brow = bn + tid;
    if (kvmode) {
        const int layer = brow >> 10;
        brow = layer * 1536 + 512 + (brow & 1023);
    }
    const __half* srcB = Bh + (size_t)brow * K + koff;
    const __half* srcA = Ah + (size_t)(bm + (tid & 127)) * K + koff;
    const uint32_t dstB = OF_B + (uint32_t)tid * SA * 2;
    const uint32_t dstA = (uint32_t)(tid & 127) * SA * 2;
    const bool doA = tid < 128;

    const int r  = lane & 7;
    const int q1 = (lane >> 3) & 1;
    const int q2 = lane >> 4;
    const uint32_t oa = (uint32_t)((wm * 64 + q1 * 8 + r) * SA + q2 * 8) * 2;
    const uint32_t ob = (uint32_t)((wn * 64 + q2 * 8 + r) * SA + q1 * 8) * 2;

    float acc[4][8][4];
#pragma unroll
    for (int i = 0; i < 4; i++)
#pragma unroll
        for (int j = 0; j < 8; j++)
#pragma unroll
            for (int t = 0; t < 4; t++) acc[i][j][t] = 0.f;

    const int niter = kc / 32;

    auto load_stage = [&](int j) {
        const uint32_t so = sb + (uint32_t)(j % 3) * STG1;
        const size_t ko = (size_t)j * 32;
        const __half* s = srcB + ko;
        const uint32_t d = so + dstB;
        cpa16(d,      s);      cpa16(d + 16, s + 8);
        cpa16(d + 32, s + 16); cpa16(d + 48, s + 24);
        if (doA) {
            const __half* sa = srcA + ko;
            const uint32_t da = so + dstA;
            cpa16(da,      sa);      cpa16(da + 16, sa + 8);
            cpa16(da + 32, sa + 16); cpa16(da + 48, sa + 24);
        }
        cpa_commit();
    };

    load_stage(0);
    load_stage(1);

    for (int i = 0; i < niter; i++) {
        asm volatile("cp.async.wait_group 1;" ::: "memory");
        __syncthreads();
        if (i + 2 < niter) load_stage(i + 2);
        else               cpa_commit();

        const uint32_t so = sb + (uint32_t)(i % 3) * STG1;
#pragma unroll
        for (int ks = 0; ks < 2; ks++) {
            const uint32_t ko = (uint32_t)ks * 32;
            uint32_t ah[4][4], bhf[4][4];
#pragma unroll
            for (int mi = 0; mi < 4; mi++) {
                const uint32_t aoff = oa + (uint32_t)(mi * 16 * SA) * 2 + ko;
                ldsm4(so + aoff, ah[mi][0], ah[mi][1], ah[mi][2], ah[mi][3]);
            }
#pragma unroll
            for (int p = 0; p < 4; p++) {
                const uint32_t boff = ob + (uint32_t)(p * 16 * SA) * 2 + ko;
                ldsm4(so + OF_B + boff, bhf[p][0], bhf[p][1], bhf[p][2], bhf[p][3]);
            }
#pragma unroll
            for (int mi = 0; mi < 4; mi++)
#pragma unroll
                for (int ni = 0; ni < 8; ni++) {
                    const int p = ni >> 1, e = (ni & 1) * 2;
                    mma16816(acc[mi][ni], ah[mi], bhf[p][e], bhf[p][e + 1]);
                }
        }
        // no trailing sync: top-of-next-iter wait+sync provides WAR ordering
    }

    const int erow = lane >> 2;
    const int ecol = (lane & 3) * 2;
#pragma unroll
    for (int mi = 0; mi < 4; mi++) {
        const int gr = bm + wm * 64 + mi * 16 + erow;
#pragma unroll
        for (int ni = 0; ni < 8; ni++) {
            const int gc = bn + wn * 64 + ni * 8 + ecol;
            float2 v0 = make_float2(acc[mi][ni][0], acc[mi][ni][1]);
            float2 v1 = make_float2(acc[mi][ni][2], acc[mi][ni][3]);
            if (bias) {
                float bx = bias[gc], by = bias[gc + 1];
                v0.x += bx; v0.y += by; v1.x += bx; v1.y += by;
            }
            if (relu) {
                v0.x = fmaxf(v0.x, 0.f); v0.y = fmaxf(v0.y, 0.f);
                v1.x = fmaxf(v1.x, 0.f); v1.y = fmaxf(v1.y, 0.f);
            }
            const size_t o0 = (size_t)gr * N + gc;
            const size_t o1 = (size_t)(gr + 8) * N + gc;
            if (Cz) {
                *(float2*)(Cz + o0) = v0;
                *(float2*)(Cz + o1) = v1;
            }
            if (Ch) {
                *(__half2*)(Ch + o0) = __floats2half2_rn(v0.x, v0.y);
                *(__half2*)(Ch + o1) = __floats2half2_rn(v1.x, v1.y);
            }
        }
    }
}

// ---------------------------------------------------------------------------
// 2-pass fp16 GEMM (A = hi+lo exact), BK=32, NST=3. Encoder/decoder only.
// ---------------------------------------------------------------------------
#define NST2  3
#define STG2  (3 * TILEB)
#define SMEM2 (NST2 * STG2)         // 92160

__global__ void __launch_bounds__(256, 2)
hgemm2_kernel(const __half* __restrict__ Ah, const __half* __restrict__ Al,
              const __half* __restrict__ Bh,
              const float* __restrict__ bias,
              float* __restrict__ C, __half* __restrict__ Ch, __half* __restrict__ Cl,
              int M, int N, int K, int relu)
{
    const uint32_t OF_A = 0, OF_AL = TILEB, OF_B = 2 * TILEB;

    extern __shared__ __half smraw[];
    const uint32_t sb = smem_u32(smraw);

    const int tid  = threadIdx.x;
    const int lane = tid & 31;
    const int wid  = tid >> 5;
    const int wm   = wid >> 2;
    const int wn   = wid & 3;
    const int bm   = blockIdx.y * 128;
    const int bn   = blockIdx.x * 128;

    const int srow = tid & 127;
    const bool loA = tid < 128;
    const __half* src0 = loA ? (Ah + (size_t)(bm + srow) * K)
                             : (Al + (size_t)(bm + srow) * K);
    const uint32_t dst0 = (loA ? OF_A : OF_AL) + (uint32_t)srow * SA * 2;
    const __half* src1 = loA ? (Bh + (size_t)(bn + srow) * K) : nullptr;
    const uint32_t dst1 = OF_B + (uint32_t)srow * SA * 2;

    const int r  = lane & 7;
    const int q1 = (lane >> 3) & 1;
    const int q2 = lane >> 4;
    const uint32_t oa = (uint32_t)((wm * 64 + q1 * 8 + r) * SA + q2 * 8) * 2;
    const uint32_t ob = (uint32_t)((wn * 32 + q2 * 8 + r) * SA + q1 * 8) * 2;

    float acc[4][4][4];
#pragma unroll
    for (int i = 0; i < 4; i++)
#pragma unroll
        for (int j = 0; j < 4; j++)
#pragma unroll
            for (int t = 0; t < 4; t++) acc[i][j][t] = 0.f;

    const int niter = K / 32;

    auto load_stage = [&](int j) {
        const uint32_t so = (uint32_t)(j % NST2) * STG2;
        const size_t ko = (size_t)j * 32;
        const __half* s = src0 + ko;
        const uint32_t d = sb + so + dst0;
        cpa16(d,      s);
        cpa16(d + 16, s + 8);
        cpa16(d + 32, s + 16);
        cpa16(d + 48, s + 24);
        if (loA) {
            const __half* s1 = src1 + ko;
            const uint32_t d1 = sb + so + dst1;
            cpa16(d1,      s1);
            cpa16(d1 + 16, s1 + 8);
            cpa16(d1 + 32, s1 + 16);
            cpa16(d1 + 48, s1 + 24);
        }
        cpa_commit();
    };

#pragma unroll
    for (int j = 0; j < NST2 - 1; j++) {
        if (j < niter) load_stage(j);
        else           cpa_commit();
    }

    for (int i = 0; i < niter; i++) {
        asm volatile("cp.async.wait_group 1;" ::: "memory");
        __syncthreads();
        if (i + NST2 - 1 < niter) load_stage(i + NST2 - 1);
        else                      cpa_commit();

        const uint32_t so = sb + (uint32_t)(i % NST2) * STG2;
#pragma unroll
        for (int ks = 0; ks < 2; ks++) {
            const uint32_t ko = (uint32_t)ks * 32;
            uint32_t ah[4][4], al[4][4], bhf[2][4];
#pragma unroll
            for (int mi = 0; mi < 4; mi++) {
                const uint32_t aoff = oa + (uint32_t)(mi * 16 * SA) * 2 + ko;
                ldsm4(so + OF_A + aoff,  ah[mi][0], ah[mi][1], ah[mi][2], ah[mi][3]);
                ldsm4(so + OF_AL + aoff, al[mi][0], al[mi][1], al[mi][2], al[mi][3]);
            }
#pragma unroll
            for (int p = 0; p < 2; p++) {
                const uint32_t boff = ob + (uint32_t)(p * 16 * SA) * 2 + ko;
                ldsm4(so + OF_B + boff, bhf[p][0], bhf[p][1], bhf[p][2], bhf[p][3]);
            }
#pragma unroll
            for (int mi = 0; mi < 4; mi++)
#pragma unroll
                for (int ni = 0; ni < 4; ni++) {
                    const int p = ni >> 1, e = (ni & 1) * 2;
                    mma16816(acc[mi][ni], ah[mi], bhf[p][e], bhf[p][e + 1]);
                }
#pragma unroll
            for (int mi = 0; mi < 4; mi++)
#pragma unroll
                for (int ni = 0; ni < 4; ni++) {
                    const int p = ni >> 1, e = (ni & 1) * 2;
                    mma16816(acc[mi][ni], al[mi], bhf[p][e], bhf[p][e + 1]);
                }
        }
    }

    const int erow = lane >> 2;
    const int ecol = (lane & 3) * 2;
#pragma unroll
    for (int mi = 0; mi < 4; mi++) {
        const int gr = bm + wm * 64 + mi * 16 + erow;
#pragma unroll
        for (int ni = 0; ni < 4; ni++) {
            const int gc = bn + wn * 32 + ni * 8 + ecol;
            float2 v0 = make_float2(acc[mi][ni][0], acc[mi][ni][1]);
            float2 v1 = make_float2(acc[mi][ni][2], acc[mi][ni][3]);
            if (bias) {
                float bx = bias[gc], by = bias[gc + 1];
                v0.x += bx; v0.y += by; v1.x += bx; v1.y += by;
            }
            if (relu) {
                v0.x = fmaxf(v0.x, 0.f); v0.y = fmaxf(v0.y, 0.f);
                v1.x = fmaxf(v1.x, 0.f); v1.y = fmaxf(v1.y, 0.f);
            }
            const size_t o0 = (size_t)gr * N + gc;
            const size_t o1 = (size_t)(gr + 8) * N + gc;
            if (C) {
                *(float2*)(C + o0) = v0;
                *(float2*)(C + o1) = v1;
            }
            if (Ch) {
                __half2 h0, l0, h1, l1;
                split2(v0.x, v0.y, h0, l0);
                split2(v1.x, v1.y, h1, l1);
                *(__half2*)(Ch + o0) = h0;
                *(__half2*)(Ch + o1) = h1;
                if (Cl) {
                    *(__half2*)(Cl + o0) = l0;
                    *(__half2*)(Cl + o1) = l1;
                }
            }
        }
    }
}

// ---------------------------------------------------------------------------
// Weight transpose + fp16 convert
// ---------------------------------------------------------------------------
__global__ void wconv_kernel(const float* __restrict__ W,
                             __half* __restrict__ Th,
                             int K, int N,
                             size_t inLS, size_t outLS, int rowOff)
{
    __shared__ float t[32][33];
    const float* Wz = W + (size_t)blockIdx.z * inLS;
    __half* Thz = Th + (size_t)blockIdx.z * outLS;
    const int n0 = blockIdx.x * 32, k0 = blockIdx.y * 32;
    const int tx = threadIdx.x, ty = threadIdx.y;
#pragma unroll
    for (int i = 0; i < 32; i += 8)
        t[ty + i][tx] = (n0 + tx < N) ? Wz[(size_t)(k0 + ty + i) * N + n0 + tx] : 0.f;
    __syncthreads();
#pragma unroll
    for (int i = 0; i < 32; i += 8) {
        float f = t[tx][ty + i];
        Thz[(size_t)(rowOff + n0 + ty + i) * K + k0 + tx] = __float2half_rn(f);
    }
}

// Fused Wq/Wk/Wv + Wenc transpose: grid.x covers 3*16 (qkv) + 16 (wenc).
__global__ void wconv4_kernel(const float* __restrict__ Wq,
                              const float* __restrict__ Wk,
                              const float* __restrict__ Wv,
                              const float* __restrict__ Wenc,
                              __half* __restrict__ Tqkv,
                              __half* __restrict__ Tenc)
{
    __shared__ float t[32][33];
    const int nb  = DD / 32;                 // 16
    const int mat = blockIdx.x / nb;         // 0..3
    const int n0  = (blockIdx.x - mat * nb) * 32;
    const int k0  = blockIdx.y * 32;
    const int tx = threadIdx.x, ty = threadIdx.y;

    if (mat < 3) {
        const float* W = (mat == 0 ? Wq : (mat == 1 ? Wk : Wv))
                         + (size_t)blockIdx.z * DD * DD;
        __half* Thz = Tqkv + (size_t)blockIdx.z * 3 * DD * DD + (size_t)mat * DD * DD;
#pragma unroll
        for (int i = 0; i < 32; i += 8)
            t[ty + i][tx] = W[(size_t)(k0 + ty + i) * DD + n0 + tx];
        __syncthreads();
#pragma unroll
        for (int i = 0; i < 32; i += 8)
            Thz[(size_t)(n0 + ty + i) * DD + k0 + tx] = __float2half_rn(t[tx][ty + i]);
    } else {
        if (blockIdx.z != 0 || k0 >= KENC) return;
#pragma unroll
        for (int i = 0; i < 32; i += 8)
            t[ty + i][tx] = Wenc[(size_t)(k0 + ty + i) * DD + n0 + tx];
        __syncthreads();
#pragma unroll
        for (int i = 0; i < 32; i += 8)
            Tenc[(size_t)(n0 + ty + i) * KENC + k0 + tx] = __float2half_rn(t[tx][ty + i]);
    }
}

// ---------------------------------------------------------------------------
// Concat positional encoding + fp16 hi/lo split
// ---------------------------------------------------------------------------
__global__ void concat_pe_split(const float* __restrict__ x,
                                __half* __restrict__ xh, __half* __restrict__ xl)
{
    int idx = blockIdx.x * 256 + threadIdx.x;
    if (idx >= MROWS * KENC) return;
    int row = idx >> 7;
    int c   = idx & 127;
    float val;
    if (c < EE) val = x[(size_t)row * EE + c];
    else        val = (float)(row % NN) * (1.f / (float)(NN - 1));
    __half h = __float2half_rn(val);
    xh[idx] = h;
    xl[idx] = __float2half_rn(val - __half2float(h));
}

// ---------------------------------------------------------------------------
// Decoder strip copy
// ---------------------------------------------------------------------------
__global__ void dec_copy_kernel(const float* __restrict__ dec,
                                const float* __restrict__ bias,
                                float* __restrict__ out)
{
    int idx = blockIdx.x * 256 + threadIdx.x;
    if (idx >= MROWS * EE) return;
    int row = idx / EE;
    int c   = idx - row * EE;
    out[idx] = dec[(size_t)row * 128 + c] + bias[c];
}

// ---------------------------------------------------------------------------
// Batched diagonal-softmax attention: one block per (h, b).
// ---------------------------------------------------------------------------
__global__ void __launch_bounds__(256)
batt_kernel(const float* __restrict__ q, const float* __restrict__ q2, int ldq,
            const float* __restrict__ k, int ldk,
            const float* __restrict__ v, int ldv,
            __half* __restrict__ oh, int masked)
{
    __shared__ float kT[64][160];   // [d][m], cols 144..159 zeroed

    const int h = blockIdx.x, b = blockIdx.y;
    const int tid  = threadIdx.x;
    const int lane = tid & 31;
    const int w    = tid >> 5;      // 0..7
    const int hoff = h * DK;
    const int rb   = b * NN;

    for (int idx = tid; idx < 64 * 16; idx += 256)
        kT[idx >> 4][144 + (idx & 15)] = 0.f;
    for (int idx = tid; idx < NN * 16; idx += 256) {
        const int m = idx >> 4, c = (idx & 15) * 4;
        const float4 kv = *(const float4*)(k + (size_t)(rb + m) * ldk + hoff + c);
        kT[c + 0][m] = kv.x;
        kT[c + 1][m] = kv.y;
        kT[c + 2][m] = kv.z;
        kT[c + 3][m] = kv.w;
    }
    __syncthreads();

    for (int n = w; n < NN; n += 8) {
        const int row = rb + n;
        float q0 = q[(size_t)row * ldq + hoff + lane];
        float q1 = q[(size_t)row * ldq + hoff + 32 + lane];
        if (q2) {
            q0 += q2[(size_t)row * ldq + hoff + lane];
            q1 += q2[(size_t)row * ldq + hoff + 32 + lane];
        }

        float s0 = 0.f, s1 = 0.f, s2 = 0.f, s3 = 0.f, s4 = 0.f;
#pragma unroll
        for (int d = 0; d < 32; d++) {
            const float qd = __shfl_sync(0xffffffffu, q0, d);
            s0 += qd * kT[d][lane];
            s1 += qd * kT[d][lane + 32];
            s2 += qd * kT[d][lane + 64];
            s3 += qd * kT[d][lane + 96];
            s4 += qd * kT[d][lane + 128];
        }
#pragma unroll
        for (int d = 0; d < 32; d++) {
            const float qd = __shfl_sync(0xffffffffu, q1, d);
            s0 += qd * kT[32 + d][lane];
            s1 += qd * kT[32 + d][lane + 32];
            s2 += qd * kT[32 + d][lane + 64];
            s3 += qd * kT[32 + d][lane + 96];
            s4 += qd * kT[32 + d][lane + 128];
        }

        float tmp = (n < 32) ? s0 : (n < 64) ? s1 : (n < 96) ? s2
                  : (n < 128) ? s3 : s4;
        const float sd = __shfl_sync(0xffffffffu, tmp, n & 31);

        const int mlim = masked ? (n + 1) : NN;
        if (lane       >= mlim) s0 = -3.0e38f;
        if (lane + 32  >= mlim) s1 = -3.0e38f;
        if (lane + 64  >= mlim) s2 = -3.0e38f;
        if (lane + 96  >= mlim) s3 = -3.0e38f;
        if (lane + 128 >= mlim) s4 = -3.0e38f;

        float mx = fmaxf(fmaxf(fmaxf(s0, s1), fmaxf(s2, s3)), s4);
#pragma unroll
        for (int o = 16; o; o >>= 1) mx = fmaxf(mx, __shfl_xor_sync(0xffffffffu, mx, o));

        float e = expf(s0 - mx) + expf(s1 - mx) + expf(s2 - mx)
                + expf(s3 - mx) + expf(s4 - mx);
#pragma unroll
        for (int o = 16; o; o >>= 1) e += __shfl_xor_sync(0xffffffffu, e, o);

        const float dcoef = expf(sd - mx) / e;

        const float2 vv = *(const float2*)(v + (size_t)row * ldv + hoff + lane * 2);
        *(__half2*)(oh + (size_t)row * DD + hoff + lane * 2) =
            __floats2half2_rn(dcoef * vv.x, dcoef * vv.y);
    }
}

// ---------------------------------------------------------------------------
// Fused residual add + LayerNorm (D=512), shuffle reductions.
// ---------------------------------------------------------------------------
__global__ void __launch_bounds__(256)
add_ln_kernel(const float* __restrict__ a, const float* __restrict__ a2,
              const float* __restrict__ bias,
              const float* __restrict__ r,
              const float* __restrict__ g, const float* __restrict__ beta,
              float* __restrict__ out,
              __half* __restrict__ oh, __half* __restrict__ ol)
{
    const int row = blockIdx.x;
    const int t = threadIdx.x;
    __shared__ float red1[8];
    __shared__ float red2[8];

    const size_t base = (size_t)row * DD;
    float x0 = a[base + t]       + r[base + t];
    float x1 = a[base + 256 + t] + r[base + 256 + t];
    if (a2)   { x0 += a2[base + t]; x1 += a2[base + 256 + t]; }
    if (bias) { x0 += bias[t];      x1 += bias[256 + t]; }

    float s = x0 + x1;
#pragma unroll
    for (int o = 16; o; o >>= 1) s += __shfl_xor_sync(0xffffffffu, s, o);
    if ((t & 31) == 0) red1[t >> 5] = s;
    __syncthreads();
    const float mean = (red1[0] + red1[1] + red1[2] + red1[3] +
                        red1[4] + red1[5] + red1[6] + red1[7]) * (1.f / (float)DD);

    const float d0 = x0 - mean, d1 = x1 - mean;
    float vv = d0 * d0 + d1 * d1;
#pragma unroll
    for (int o = 16; o; o >>= 1) vv += __shfl_xor_sync(0xffffffffu, vv, o);
    if ((t & 31) == 0) red2[t >> 5] = vv;
    __syncthreads();
    const float var = (red2[0] + red2[1] + red2[2] + red2[3] +
                       red2[4] + red2[5] + red2[6] + red2[7]) * (1.f / (float)DD);
    const float inv = rsqrtf(var + 1e-5f);

    const float y0 = d0 * inv * g[t]       + beta[t];
    const float y1 = d1 * inv * g[256 + t] + beta[256 + t];
    if (out) {
        out[base + t]       = y0;
        out[base + 256 + t] = y1;
    }
    if (oh) {
        __half h0 = __float2half_rn(y0);
        __half h1 = __float2half_rn(y1);
        oh[base + t]       = h0;
        oh[base + 256 + t] = h1;
        if (ol) {
            ol[base + t]       = __float2half_rn(y0 - __half2float(h0));
            ol[base + 256 + t] = __float2half_rn(y1 - __half2float(h1));
        }
    }
}

// ---------------------------------------------------------------------------
// Host orchestration
// ---------------------------------------------------------------------------
static inline void hgemm1s(const __half* Ah, const __half* Bh,
                           const float* bias, float* C, __half* Ch,
                           int M, int N, int K, int relu)
{
    dim3 grid(N / 128, M / 128, 1);
    hgemm1s_kernel<<<grid, 256, SMEM1S>>>(Ah, Bh, bias, C, Ch, M, N, K, relu);
}

static inline void hgemm1(const __half* Ah, const __half* Bh,
                          const float* bias, float* C, __half* Ch,
                          int M, int N, int K, int relu, int splitk = 1, int kvmode = 0)
{
    dim3 grid(N / 256, M / 128, splitk);
    hgemm1_kernel<<<grid, 256, SMEM1>>>(Ah, Bh, bias, C, Ch, M, N, K, relu, kvmode);
}

static inline void hgemm2(const __half* Ah, const __half* Al, const __half* Bh,
                          const float* bias, float* C, __half* Ch, __half* Cl,
                          int M, int N, int K, int relu)
{
    dim3 grid(N / 128, M / 128, 1);
    hgemm2_kernel<<<grid, 256, SMEM2>>>(Ah, Al, Bh, bias, C, Ch, Cl, M, N, K, relu);
}

extern "C" void kernel_launch(void* const* d_in, const int* in_sizes, int n_in,
                              void* d_out, int out_size)
{
    const float* x    = (const float*)d_in[1];
    const float* Wenc = (const float*)d_in[3];
    const float* benc = (const float*)d_in[4];
    const float* Wq   = (const float*)d_in[5];
    const float* Wk   = (const float*)d_in[6];
    const float* Wv   = (const float*)d_in[7];
    const float* Wo   = (const float*)d_in[8];
    const float* bo   = (const float*)d_in[9];
    const float* ln1g = (const float*)d_in[10];
    const float* ln1b = (const float*)d_in[11];
    const float* ln2g = (const float*)d_in[12];
    const float* ln2b = (const float*)d_in[13];
    const float* ln3g = (const float*)d_in[14];
    const float* ln3b = (const float*)d_in[15];
    const float* W1   = (const float*)d_in[16];
    const float* b1   = (const float*)d_in[17];
    const float* W2   = (const float*)d_in[18];
    const float* b2   = (const float*)d_in[19];
    const float* Wdec = (const float*)d_in[20];
    const float* bdec = (const float*)d_in[21];

    float *p_xe, *p_qkv, *p_kv4, *p_a2, *p_ao, *p_part, *p_dec;
    cudaGetSymbolAddress((void**)&p_xe,   g_xe);
    cudaGetSymbolAddress((void**)&p_qkv,  g_qkv);
    cudaGetSymbolAddress((void**)&p_kv4,  g_kv4);
    cudaGetSymbolAddress((void**)&p_a2,   g_a2);
    cudaGetSymbolAddress((void**)&p_ao,   g_ao);
    cudaGetSymbolAddress((void**)&p_part, g_part);
    cudaGetSymbolAddress((void**)&p_dec,  g_dec);

    __half *xp_h, *xp_l, *xe_h, *cur_h, *cur_l, *qln_h, *at_h, *a2_h, *ao_h, *hid_h;
    cudaGetSymbolAddress((void**)&xp_h,  g_xp_h);
    cudaGetSymbolAddress((void**)&xp_l,  g_xp_l);
    cudaGetSymbolAddress((void**)&xe_h,  g_xe_h);
    cudaGetSymbolAddress((void**)&cur_h, g_cur_h);
    cudaGetSymbolAddress((void**)&cur_l, g_cur_l);
    cudaGetSymbolAddress((void**)&qln_h, g_qln_h);
    cudaGetSymbolAddress((void**)&at_h,  g_at_h);
    cudaGetSymbolAddress((void**)&a2_h,  g_a2_h);
    cudaGetSymbolAddress((void**)&ao_h,  g_ao_h);
    cudaGetSymbolAddress((void**)&hid_h, g_hid_h);

    __half *wqkv, *wo, *w1, *w2, *wenc, *wdec;
    cudaGetSymbolAddress((void**)&wqkv, g_wqkvT);
    cudaGetSymbolAddress((void**)&wo,   g_woT);
    cudaGetSymbolAddress((void**)&w1,   g_w1T);
    cudaGetSymbolAddress((void**)&w2,   g_w2T);
    cudaGetSymbolAddress((void**)&wenc, g_wencT);
    cudaGetSymbolAddress((void**)&wdec, g_wdecT);

    cudaFuncSetAttribute((const void*)hgemm1s_kernel,
                         cudaFuncAttributeMaxDynamicSharedMemorySize, SMEM1S);
    cudaFuncSetAttribute((const void*)hgemm1_kernel,
                         cudaFuncAttributeMaxDynamicSharedMemorySize, SMEM1);
    cudaFuncSetAttribute((const void*)hgemm2_kernel,
                         cudaFuncAttributeMaxDynamicSharedMemorySize, SMEM2);

    dim3 wb(32, 8);
    const size_t dd2 = (size_t)DD * DD;
    const size_t df  = (size_t)DD * FF;
    dim3 batt_grid(HH, BB);
    float* part1 = p_part + (size_t)MROWS * DD;

    // [1] fused QKV + Wenc weight conversion
    wconv4_kernel<<<dim3(4 * (DD/32), DD/32, LL), wb>>>(Wq, Wk, Wv, Wenc, wqkv, wenc);
    // [2] input concat+split
    concat_pe_split<<<(MROWS * KENC + 255) / 256, 256>>>(x, xp_h, xp_l);
    // [3] encoder GEMM (2-pass)
    hgemm2(xp_h, xp_l, wenc, benc, p_xe, xe_h, nullptr, MROWS, DD, KENC, 0);
    // [4] layer-0 QKV GEMM
    hgemm1s(xe_h, wqkv, nullptr, p_qkv, nullptr, MROWS, 3 * DD, DD, 0);
    // [5] ALL layers' MHA2 K/V projections in one wide GEMM (xe-only dependent)
    hgemm1(xe_h, wqkv, nullptr, p_kv4, nullptr, MROWS, 4 * 1024, DD, 0, 1, 1);
    // [6..9] remaining weights
    wconv_kernel<<<dim3(DD/32, DD/32, LL), wb>>>(Wo, wo, DD, DD, dd2, dd2, 0);
    wconv_kernel<<<dim3(FF/32, DD/32, LL), wb>>>(W1, w1, DD, FF, df, df, 0);
    wconv_kernel<<<dim3(DD/32, FF/32, LL), wb>>>(W2, w2, FF, DD, df, df, 0);
    wconv_kernel<<<dim3(4, DD/32, 1), wb>>>(Wdec, wdec, DD, EE, 0, 0, 0);

    for (int l = 0; l < LL; l++) {
        const __half* in_h = (l == 0) ? xe_h : cur_h;
        const __half* wqkv_l = wqkv + (size_t)l * 3 * DD * DD;
        const __half* wo_l   = wo + (size_t)l * DD * DD;
        const __half* w1_l   = w1 + (size_t)l * DD * FF;
        const __half* w2_l   = w2 + (size_t)l * DD * FF;
        const float* bol = bo + (size_t)l * DD;
        const float* b1l = b1 + (size_t)l * FF;
        const float* b2l = b2 + (size_t)l * DD;
        const float* kv_l = p_kv4 + (size_t)l * 1024;   // k cols [0,512), v cols [512,1024)

        // --- MHA1 (causal): fused QKV (layer 0's already launched) ---
        if (l > 0)
            hgemm1s(in_h, wqkv_l, nullptr, p_qkv, nullptr, MROWS, 3 * DD, DD, 0);
        batt_kernel<<<batt_grid, 256>>>(p_qkv, nullptr, 3 * DD,
                                        p_qkv + DD, 3 * DD,
                                        p_qkv + 2 * DD, 3 * DD, at_h, 1);
        hgemm1s(at_h, wo_l, bol, p_part, nullptr, MROWS, DD, DD, 0);
        add_ln_kernel<<<MROWS, 256>>>(p_part, nullptr, nullptr, p_xe,
                                      ln1g + (size_t)l * DD, ln1b + (size_t)l * DD,
                                      nullptr, qln_h, nullptr);

        // --- MHA2 (no mask): Q projection; K/V from precomputed kv4 ---
        hgemm1s(qln_h, wqkv_l, nullptr, p_part, nullptr, MROWS, DD, DD, 0);
        batt_kernel<<<batt_grid, 256>>>(p_part, nullptr, DD,
                                        kv_l, 4 * 1024,
                                        kv_l + DD, 4 * 1024, at_h, 0);
        hgemm1s(at_h, wo_l, bol, p_a2, a2_h, MROWS, DD, DD, 0);

        // --- FF stack 1 (wide tiles; W2 split-K=2 combined in add_ln) ---
        hgemm1(a2_h, w1_l, b1l, nullptr, hid_h, MROWS, FF, DD, 1);
        hgemm1(hid_h, w2_l, nullptr, p_part, nullptr, MROWS, DD, FF, 0, 2);
        add_ln_kernel<<<MROWS, 256>>>(p_part, part1, b2l, p_a2,
                                      ln2g + (size_t)l * DD, ln2b + (size_t)l * DD,
                                      p_ao, ao_h, nullptr);

        // --- FF stack 2 ---
        hgemm1(ao_h, w1_l, b1l, nullptr, hid_h, MROWS, FF, DD, 1);
        hgemm1(hid_h, w2_l, nullptr, p_part, nullptr, MROWS, DD, FF, 0, 2);
        add_ln_kernel<<<MROWS, 256>>>(p_part, part1, b2l, p_ao,
                                      ln3g + (size_t)l * DD, ln3b + (size_t)l * DD,
                                      nullptr, cur_h, cur_l);
    }

    // --- Decoder (2-pass, padded N=128) ---
    hgemm2(cur_h, cur_l, wdec, nullptr, p_dec, nullptr, nullptr, MROWS, 128, DD, 0);
    dec_copy_kernel<<<(MROWS * EE + 255) / 256, 256>>>(p_dec, bdec, (float*)d_out);
}